// round 9
// baseline (speedup 1.0000x reference)
#include <cuda_runtime.h>

#define S_TOT 2000
#define A_TOT 1000
#define I_DIM 5
#define H_DIM 32
#define PAIRS (S_TOT / 2)
#define SPLIT 2                       // pair-range splits per atom (grid.y)
#define PAIRS_PER_BLK (PAIRS / SPLIT)
#define NTHREADS 256

typedef unsigned long long ull;

// ---- packed f32x2 helpers (sm_103a) ----
__device__ __forceinline__ ull pack2(float lo, float hi) {
    ull r; asm("mov.b64 %0, {%1, %2};" : "=l"(r) : "f"(lo), "f"(hi)); return r;
}
__device__ __forceinline__ void unpack2(ull v, float& lo, float& hi) {
    asm("mov.b64 {%0, %1}, %2;" : "=f"(lo), "=f"(hi) : "l"(v));
}
__device__ __forceinline__ ull fma2(ull a, ull b, ull c) {
    ull d; asm("fma.rn.f32x2 %0, %1, %2, %3;" : "=l"(d) : "l"(a), "l"(b), "l"(c)); return d;
}
__device__ __forceinline__ ull tanh2(ull x) {
    float lo, hi; unpack2(x, lo, hi);
    asm("tanh.approx.f32 %0, %0;" : "+f"(lo));
    asm("tanh.approx.f32 %0, %0;" : "+f"(hi));
    return pack2(lo, hi);
}

__global__ __launch_bounds__(NTHREADS, 2) void mlp_kernel(
    const float* __restrict__ g,   // [S, A, I]
    const float* __restrict__ W1,  // [A, I, H]
    const float* __restrict__ b1,  // [A, H]
    const float* __restrict__ W2,  // [A, H, H]
    const float* __restrict__ b2,  // [A, H]
    const float* __restrict__ W3,  // [A, H, 1]
    const float* __restrict__ b3,  // [A, 1]
    float* __restrict__ out)       // [S, A]
{
    // Weights duplicated ({w,w}) in smem so each packed FMA reads one 64-bit
    // broadcast operand serving BOTH structures of the pair.
    __shared__ __align__(16) ull w1t[H_DIM * I_DIM];     // transposed: [j][i]
    __shared__ __align__(16) ull w2d[H_DIM * H_DIM];     // [j][k]
    __shared__ __align__(16) ull b1d[H_DIM];
    __shared__ __align__(16) ull b2d[H_DIM];
    __shared__ __align__(16) ull w3d[H_DIM];
    __shared__ ull b3d;

    const int a   = blockIdx.x;
    const int tid = threadIdx.x;

    for (int idx = tid; idx < I_DIM * H_DIM; idx += NTHREADS) {
        int i = idx / H_DIM, j = idx % H_DIM;
        float w = W1[a * I_DIM * H_DIM + idx];
        w1t[j * I_DIM + i] = pack2(w, w);
    }
    for (int idx = tid; idx < H_DIM * H_DIM; idx += NTHREADS) {
        float w = W2[a * H_DIM * H_DIM + idx];
        w2d[idx] = pack2(w, w);
    }
    if (tid < H_DIM) {
        float x;
        x = b1[a * H_DIM + tid]; b1d[tid] = pack2(x, x);
        x = b2[a * H_DIM + tid]; b2d[tid] = pack2(x, x);
        x = W3[a * H_DIM + tid]; w3d[tid] = pack2(x, x);
    }
    if (tid == 0) { float x = b3[a]; b3d = pack2(x, x); }
    __syncthreads();

    const int p_base = blockIdx.y * PAIRS_PER_BLK;

    #pragma unroll 1
    for (int t = tid; t < PAIRS_PER_BLK; t += NTHREADS) {
        const int s0 = 2 * (p_base + t);
        const float* g0 = g + (size_t)s0 * (A_TOT * I_DIM) + a * I_DIM;
        const float* g1 = g0 + A_TOT * I_DIM;

        ull gx[I_DIM];
        #pragma unroll
        for (int i = 0; i < I_DIM; i++) gx[i] = pack2(g0[i], g1[i]);

        ull acc[H_DIM];
        #pragma unroll
        for (int k = 0; k < H_DIM; k++) acc[k] = b2d[k];

        // CRITICAL: unroll 1 (round-8 lesson). Full unroll lets ptxas batch-
        // hoist all 32x8 LDS loads -> reg blowup -> acc[] spill -> DRAM
        // thrash. One j-iteration in flight keeps live regs ~110.
        #pragma unroll 1
        for (int j = 0; j < H_DIM; j++) {
            ull a1 = b1d[j];
            #pragma unroll
            for (int i = 0; i < I_DIM; i++)
                a1 = fma2(gx[i], w1t[j * I_DIM + i], a1);
            const ull hj = tanh2(a1);

            const ulonglong2* row = (const ulonglong2*)&w2d[j * H_DIM];
            #pragma unroll
            for (int q = 0; q < H_DIM / 2; q++) {
                const ulonglong2 w = row[q];
                acc[2 * q]     = fma2(hj, w.x, acc[2 * q]);
                acc[2 * q + 1] = fma2(hj, w.y, acc[2 * q + 1]);
            }
        }

        // ---- layer 3: e = tanh(acc) . W3 + b3 ----
        ull e = b3d;
        #pragma unroll
        for (int k = 0; k < H_DIM; k++)
            e = fma2(tanh2(acc[k]), w3d[k], e);

        float e0, e1; unpack2(e, e0, e1);
        out[(size_t)s0 * A_TOT + a]       = e0;
        out[(size_t)(s0 + 1) * A_TOT + a] = e1;
    }
}

extern "C" void kernel_launch(void* const* d_in, const int* in_sizes, int n_in,
                              void* d_out, int out_size) {
    const float* g  = (const float*)d_in[0];
    const float* W1 = (const float*)d_in[1];
    const float* b1 = (const float*)d_in[2];
    const float* W2 = (const float*)d_in[3];
    const float* b2 = (const float*)d_in[4];
    const float* W3 = (const float*)d_in[5];
    const float* b3 = (const float*)d_in[6];
    float* out = (float*)d_out;

    dim3 grid(A_TOT, SPLIT);
    mlp_kernel<<<grid, NTHREADS>>>(g, W1, b1, W2, b2, W3, b3, out);
}

// round 10
// speedup vs baseline: 1.2008x; 1.2008x over previous
#include <cuda_runtime.h>

#define S_TOT 2000
#define A_TOT 1000
#define I_DIM 5
#define H_DIM 32
#define SPLIT 2                       // struct-range splits per atom (grid.y)
#define S_PER_BLK (S_TOT / SPLIT)
#define NTHREADS 256
#define W1_STRIDE 8                   // padded: w1[0..4], b1 in slot 5, 2x float4/row

__device__ __forceinline__ float tanh_fast(float x) {
    asm("tanh.approx.f32 %0, %0;" : "+f"(x));
    return x;
}

// 3 blocks/SM -> 85-reg cap -> 24 warps/SM (occupancy lever; true live set ~70)
__global__ __launch_bounds__(NTHREADS, 3) void mlp_kernel(
    const float* __restrict__ g,   // [S, A, I]
    const float* __restrict__ W1,  // [A, I, H]
    const float* __restrict__ b1,  // [A, H]
    const float* __restrict__ W2,  // [A, H, H]
    const float* __restrict__ b2,  // [A, H]
    const float* __restrict__ W3,  // [A, H, 1]
    const float* __restrict__ b3,  // [A, 1]
    float* __restrict__ out)       // [S, A]
{
    // Scalar weights in smem; all inner-loop addresses warp-uniform ->
    // conflict-free broadcast.
    __shared__ __align__(16) float w1p[H_DIM * W1_STRIDE]; // [j][0..4]=W1, [j][5]=b1
    __shared__ __align__(16) float w2s[H_DIM * H_DIM];     // [j][k], float4 rows
    __shared__ __align__(16) float b2s[H_DIM];
    __shared__ __align__(16) float w3s[H_DIM];
    __shared__ float b3s;

    const int a   = blockIdx.x;
    const int tid = threadIdx.x;

    for (int idx = tid; idx < H_DIM * W1_STRIDE; idx += NTHREADS) {
        int j = idx / W1_STRIDE, slot = idx % W1_STRIDE;
        float v = 0.0f;
        if (slot < I_DIM)       v = W1[a * I_DIM * H_DIM + slot * H_DIM + j];
        else if (slot == I_DIM) v = b1[a * H_DIM + j];
        w1p[idx] = v;
    }
    for (int idx = tid; idx < H_DIM * H_DIM; idx += NTHREADS)
        w2s[idx] = W2[a * H_DIM * H_DIM + idx];
    if (tid < H_DIM) {
        b2s[tid] = b2[a * H_DIM + tid];
        w3s[tid] = W3[a * H_DIM + tid];
    }
    if (tid == 0) b3s = b3[a];
    __syncthreads();

    const int s_base = blockIdx.y * S_PER_BLK;

    #pragma unroll 1
    for (int t = tid; t < S_PER_BLK; t += NTHREADS) {
        const int s = s_base + t;
        const float* gp = g + (size_t)s * (A_TOT * I_DIM) + a * I_DIM;

        float gv[I_DIM];
        #pragma unroll
        for (int i = 0; i < I_DIM; i++) gv[i] = gp[i];

        float acc[H_DIM];
        #pragma unroll
        for (int k = 0; k < H_DIM; k++) acc[k] = b2s[k];

        // CRITICAL: unroll 1 (round-8 lesson). Full unroll lets ptxas batch-
        // hoist all the LDS loads -> reg blowup -> acc[] spill -> DRAM thrash.
        #pragma unroll 1
        for (int j = 0; j < H_DIM; j++) {
            const float4* w1row = (const float4*)&w1p[j * W1_STRIDE];
            const float4 wlo = w1row[0];           // w1_0..3
            const float4 whi = w1row[1];           // w1_4, b1_j, pad, pad
            float a1 = whi.y;                      // b1_j
            a1 = fmaf(gv[0], wlo.x, a1);
            a1 = fmaf(gv[1], wlo.y, a1);
            a1 = fmaf(gv[2], wlo.z, a1);
            a1 = fmaf(gv[3], wlo.w, a1);
            a1 = fmaf(gv[4], whi.x, a1);
            const float hj = tanh_fast(a1);

            const float4* row = (const float4*)&w2s[j * H_DIM];
            #pragma unroll
            for (int q = 0; q < H_DIM / 4; q++) {
                const float4 w = row[q];
                acc[4 * q + 0] = fmaf(hj, w.x, acc[4 * q + 0]);
                acc[4 * q + 1] = fmaf(hj, w.y, acc[4 * q + 1]);
                acc[4 * q + 2] = fmaf(hj, w.z, acc[4 * q + 2]);
                acc[4 * q + 3] = fmaf(hj, w.w, acc[4 * q + 3]);
            }
        }

        // ---- layer 3: e = tanh(acc) . W3 + b3 ----
        float e = b3s;
        #pragma unroll
        for (int k = 0; k < H_DIM; k++)
            e = fmaf(tanh_fast(acc[k]), w3s[k], e);

        out[(size_t)s * A_TOT + a] = e;
    }
}

extern "C" void kernel_launch(void* const* d_in, const int* in_sizes, int n_in,
                              void* d_out, int out_size) {
    const float* g  = (const float*)d_in[0];
    const float* W1 = (const float*)d_in[1];
    const float* b1 = (const float*)d_in[2];
    const float* W2 = (const float*)d_in[3];
    const float* b2 = (const float*)d_in[4];
    const float* W3 = (const float*)d_in[5];
    const float* b3 = (const float*)d_in[6];
    float* out = (float*)d_out;

    dim3 grid(A_TOT, SPLIT);
    mlp_kernel<<<grid, NTHREADS>>>(g, W1, b1, W2, b2, W3, b3, out);
}

// round 11
// speedup vs baseline: 1.2296x; 1.0240x over previous
#include <cuda_runtime.h>

#define S_TOT 2000
#define A_TOT 1000
#define I_DIM 5
#define H_DIM 32
#define SPLIT 2                       // struct-range splits per atom (grid.y)
#define S_PER_BLK (S_TOT / SPLIT)
#define NTHREADS 256
#define W1_STRIDE 8                   // padded: w1[0..4], b1 in slot 5, 2x float4/row

__device__ __forceinline__ float tanh_fast(float x) {
    asm("tanh.approx.f32 %0, %0;" : "+f"(x));
    return x;
}

// 4 blocks/SM -> 64-reg cap -> 32 warps/SM. True live set ~55 regs
// (acc[32] + gv[5] + one float4 temp + addressing), so 64 should fit
// without spill; occupancy is the binding resource (issue=53.8% @ 24 warps).
__global__ __launch_bounds__(NTHREADS, 4) void mlp_kernel(
    const float* __restrict__ g,   // [S, A, I]
    const float* __restrict__ W1,  // [A, I, H]
    const float* __restrict__ b1,  // [A, H]
    const float* __restrict__ W2,  // [A, H, H]
    const float* __restrict__ b2,  // [A, H]
    const float* __restrict__ W3,  // [A, H, 1]
    const float* __restrict__ b3,  // [A, 1]
    float* __restrict__ out)       // [S, A]
{
    // Scalar weights in smem; all inner-loop addresses warp-uniform ->
    // conflict-free broadcast.
    __shared__ __align__(16) float w1p[H_DIM * W1_STRIDE]; // [j][0..4]=W1, [j][5]=b1
    __shared__ __align__(16) float w2s[H_DIM * H_DIM];     // [j][k], float4 rows
    __shared__ __align__(16) float b2s[H_DIM];
    __shared__ __align__(16) float w3s[H_DIM];
    __shared__ float b3s;

    const int a   = blockIdx.x;
    const int tid = threadIdx.x;

    for (int idx = tid; idx < H_DIM * W1_STRIDE; idx += NTHREADS) {
        int j = idx / W1_STRIDE, slot = idx % W1_STRIDE;
        float v = 0.0f;
        if (slot < I_DIM)       v = W1[a * I_DIM * H_DIM + slot * H_DIM + j];
        else if (slot == I_DIM) v = b1[a * H_DIM + j];
        w1p[idx] = v;
    }
    for (int idx = tid; idx < H_DIM * H_DIM; idx += NTHREADS)
        w2s[idx] = W2[a * H_DIM * H_DIM + idx];
    if (tid < H_DIM) {
        b2s[tid] = b2[a * H_DIM + tid];
        w3s[tid] = W3[a * H_DIM + tid];
    }
    if (tid == 0) b3s = b3[a];
    __syncthreads();

    const int s_base = blockIdx.y * S_PER_BLK;

    #pragma unroll 1
    for (int t = tid; t < S_PER_BLK; t += NTHREADS) {
        const int s = s_base + t;
        const float* gp = g + (size_t)s * (A_TOT * I_DIM) + a * I_DIM;

        float gv[I_DIM];
        #pragma unroll
        for (int i = 0; i < I_DIM; i++) gv[i] = gp[i];

        float acc[H_DIM];
        #pragma unroll
        for (int k = 0; k < H_DIM; k++) acc[k] = b2s[k];

        // CRITICAL: unroll 1 (round-8 lesson). Full unroll lets ptxas batch-
        // hoist all the LDS loads -> reg blowup -> acc[] spill -> DRAM thrash.
        #pragma unroll 1
        for (int j = 0; j < H_DIM; j++) {
            const float4* w1row = (const float4*)&w1p[j * W1_STRIDE];
            const float4 wlo = w1row[0];           // w1_0..3
            const float4 whi = w1row[1];           // w1_4, b1_j, pad, pad
            float a1 = whi.y;                      // b1_j
            a1 = fmaf(gv[0], wlo.x, a1);
            a1 = fmaf(gv[1], wlo.y, a1);
            a1 = fmaf(gv[2], wlo.z, a1);
            a1 = fmaf(gv[3], wlo.w, a1);
            a1 = fmaf(gv[4], whi.x, a1);
            const float hj = tanh_fast(a1);

            const float4* row = (const float4*)&w2s[j * H_DIM];
            #pragma unroll
            for (int q = 0; q < H_DIM / 4; q++) {
                const float4 w = row[q];
                acc[4 * q + 0] = fmaf(hj, w.x, acc[4 * q + 0]);
                acc[4 * q + 1] = fmaf(hj, w.y, acc[4 * q + 1]);
                acc[4 * q + 2] = fmaf(hj, w.z, acc[4 * q + 2]);
                acc[4 * q + 3] = fmaf(hj, w.w, acc[4 * q + 3]);
            }
        }

        // ---- layer 3: e = tanh(acc) . W3 + b3 ----
        float e = b3s;
        #pragma unroll
        for (int k = 0; k < H_DIM; k++)
            e = fmaf(tanh_fast(acc[k]), w3s[k], e);

        out[(size_t)s * A_TOT + a] = e;
    }
}

extern "C" void kernel_launch(void* const* d_in, const int* in_sizes, int n_in,
                              void* d_out, int out_size) {
    const float* g  = (const float*)d_in[0];
    const float* W1 = (const float*)d_in[1];
    const float* b1 = (const float*)d_in[2];
    const float* W2 = (const float*)d_in[3];
    const float* b2 = (const float*)d_in[4];
    const float* W3 = (const float*)d_in[5];
    const float* b3 = (const float*)d_in[6];
    float* out = (float*)d_out;

    dim3 grid(A_TOT, SPLIT);
    mlp_kernel<<<grid, NTHREADS>>>(g, W1, b1, W2, b2, W3, b3, out);
}

// round 12
// speedup vs baseline: 1.4050x; 1.1426x over previous
#include <cuda_runtime.h>

#define S_TOT 2000
#define A_TOT 1000
#define I_DIM 5
#define H_DIM 32
#define PAIRS (S_TOT / 2)
#define SPLIT 2                       // pair-range splits per atom (grid.y)
#define PAIRS_PER_BLK (PAIRS / SPLIT)
#define NTHREADS 256
#define W1_STRIDE 8                   // padded: w1[0..4], b1 in slot 5, 2x float4/row

__device__ __forceinline__ float tanh_fast(float x) {
    asm("tanh.approx.f32 %0, %0;" : "+f"(x));
    return x;
}

// 2-struct ILP per thread: each W2 float4 LDS feeds 8 FMAs (4 per struct),
// halving L1 wavefront pressure per unit work (L1 was the 76% binding pipe).
// 128-reg cap (2 blocks/SM) is known spill-safe for the ~100-reg live set.
__global__ __launch_bounds__(NTHREADS, 2) void mlp_kernel(
    const float* __restrict__ g,   // [S, A, I]
    const float* __restrict__ W1,  // [A, I, H]
    const float* __restrict__ b1,  // [A, H]
    const float* __restrict__ W2,  // [A, H, H]
    const float* __restrict__ b2,  // [A, H]
    const float* __restrict__ W3,  // [A, H, 1]
    const float* __restrict__ b3,  // [A, 1]
    float* __restrict__ out)       // [S, A]
{
    __shared__ __align__(16) float w1p[H_DIM * W1_STRIDE]; // [j][0..4]=W1, [j][5]=b1
    __shared__ __align__(16) float w2s[H_DIM * H_DIM];     // [j][k], float4 rows
    __shared__ __align__(16) float b2s[H_DIM];
    __shared__ __align__(16) float w3s[H_DIM];
    __shared__ float b3s;

    const int a   = blockIdx.x;
    const int tid = threadIdx.x;

    for (int idx = tid; idx < H_DIM * W1_STRIDE; idx += NTHREADS) {
        int j = idx / W1_STRIDE, slot = idx % W1_STRIDE;
        float v = 0.0f;
        if (slot < I_DIM)       v = W1[a * I_DIM * H_DIM + slot * H_DIM + j];
        else if (slot == I_DIM) v = b1[a * H_DIM + j];
        w1p[idx] = v;
    }
    for (int idx = tid; idx < H_DIM * H_DIM; idx += NTHREADS)
        w2s[idx] = W2[a * H_DIM * H_DIM + idx];
    if (tid < H_DIM) {
        b2s[tid] = b2[a * H_DIM + tid];
        w3s[tid] = W3[a * H_DIM + tid];
    }
    if (tid == 0) b3s = b3[a];
    __syncthreads();

    const int p_base = blockIdx.y * PAIRS_PER_BLK;

    #pragma unroll 1
    for (int t = tid; t < PAIRS_PER_BLK; t += NTHREADS) {
        const int s0 = 2 * (p_base + t);
        const float* gp0 = g + (size_t)s0 * (A_TOT * I_DIM) + a * I_DIM;
        const float* gp1 = gp0 + A_TOT * I_DIM;

        float gv0[I_DIM], gv1[I_DIM];
        #pragma unroll
        for (int i = 0; i < I_DIM; i++) { gv0[i] = gp0[i]; gv1[i] = gp1[i]; }

        float acc0[H_DIM], acc1[H_DIM];
        #pragma unroll
        for (int k = 0; k < H_DIM; k++) { acc0[k] = b2s[k]; acc1[k] = b2s[k]; }

        // CRITICAL: unroll 1 (round-8 lesson): full unroll -> LDS batch-hoist
        // -> reg blowup -> acc spill -> DRAM thrash.
        #pragma unroll 1
        for (int j = 0; j < H_DIM; j++) {
            const float4* w1row = (const float4*)&w1p[j * W1_STRIDE];
            const float4 wlo = w1row[0];           // w1_0..3
            const float4 whi = w1row[1];           // w1_4, b1_j, pad, pad
            float a10 = whi.y, a11 = whi.y;        // b1_j
            a10 = fmaf(gv0[0], wlo.x, a10);  a11 = fmaf(gv1[0], wlo.x, a11);
            a10 = fmaf(gv0[1], wlo.y, a10);  a11 = fmaf(gv1[1], wlo.y, a11);
            a10 = fmaf(gv0[2], wlo.z, a10);  a11 = fmaf(gv1[2], wlo.z, a11);
            a10 = fmaf(gv0[3], wlo.w, a10);  a11 = fmaf(gv1[3], wlo.w, a11);
            a10 = fmaf(gv0[4], whi.x, a10);  a11 = fmaf(gv1[4], whi.x, a11);
            const float hj0 = tanh_fast(a10);
            const float hj1 = tanh_fast(a11);

            const float4* row = (const float4*)&w2s[j * H_DIM];
            #pragma unroll
            for (int q = 0; q < H_DIM / 4; q++) {
                const float4 w = row[q];
                acc0[4 * q + 0] = fmaf(hj0, w.x, acc0[4 * q + 0]);
                acc1[4 * q + 0] = fmaf(hj1, w.x, acc1[4 * q + 0]);
                acc0[4 * q + 1] = fmaf(hj0, w.y, acc0[4 * q + 1]);
                acc1[4 * q + 1] = fmaf(hj1, w.y, acc1[4 * q + 1]);
                acc0[4 * q + 2] = fmaf(hj0, w.z, acc0[4 * q + 2]);
                acc1[4 * q + 2] = fmaf(hj1, w.z, acc1[4 * q + 2]);
                acc0[4 * q + 3] = fmaf(hj0, w.w, acc0[4 * q + 3]);
                acc1[4 * q + 3] = fmaf(hj1, w.w, acc1[4 * q + 3]);
            }
        }

        // ---- layer 3 ----
        float e0 = b3s, e1 = b3s;
        #pragma unroll
        for (int k = 0; k < H_DIM; k++) {
            const float w3k = w3s[k];
            e0 = fmaf(tanh_fast(acc0[k]), w3k, e0);
            e1 = fmaf(tanh_fast(acc1[k]), w3k, e1);
        }

        out[(size_t)s0 * A_TOT + a]       = e0;
        out[(size_t)(s0 + 1) * A_TOT + a] = e1;
    }
}

extern "C" void kernel_launch(void* const* d_in, const int* in_sizes, int n_in,
                              void* d_out, int out_size) {
    const float* g  = (const float*)d_in[0];
    const float* W1 = (const float*)d_in[1];
    const float* b1 = (const float*)d_in[2];
    const float* W2 = (const float*)d_in[3];
    const float* b2 = (const float*)d_in[4];
    const float* W3 = (const float*)d_in[5];
    const float* b3 = (const float*)d_in[6];
    float* out = (float*)d_out;

    dim3 grid(A_TOT, SPLIT);
    mlp_kernel<<<grid, NTHREADS>>>(g, W1, b1, W2, b2, W3, b3, out);
}

// round 14
// speedup vs baseline: 2.5420x; 1.8093x over previous
#include <cuda_runtime.h>
#include <cuda_fp16.h>
#include <cstdint>

#define S_TOT 2000
#define A_TOT 1000
#define I_DIM 5
#define H_DIM 32
#define NTHREADS 256
#define NWARPS 8
#define GROUPS ((S_TOT + 31) / 32)    // 63 groups of 32 structs
#define HB_STRIDE 40                  // halves per hbuf row: conflict-free A-frag loads

__device__ __forceinline__ float tanh_fast(float x) {
    asm("tanh.approx.f32 %0, %0;" : "+f"(x));
    return x;
}

// D = A(16x16 fp16, row) * B(16x8 fp16, col) + C (fp32)
__device__ __forceinline__ void mma16816(float& c0, float& c1, float& c2, float& c3,
                                         uint32_t a0, uint32_t a1, uint32_t a2, uint32_t a3,
                                         uint32_t b0, uint32_t b1) {
    asm volatile(
        "mma.sync.aligned.m16n8k16.row.col.f32.f16.f16.f32 "
        "{%0,%1,%2,%3}, {%4,%5,%6,%7}, {%8,%9}, {%0,%1,%2,%3};"
        : "+f"(c0), "+f"(c1), "+f"(c2), "+f"(c3)
        : "r"(a0), "r"(a1), "r"(a2), "r"(a3), "r"(b0), "r"(b1));
}

__global__ __launch_bounds__(NTHREADS, 2) void mlp_kernel(
    const float* __restrict__ g,   // [S, A, I]
    const float* __restrict__ W1,  // [A, I, H]
    const float* __restrict__ b1,  // [A, H]
    const float* __restrict__ W2,  // [A, H, H]
    const float* __restrict__ b2,  // [A, H]
    const float* __restrict__ W3,  // [A, H, 1]
    const float* __restrict__ b3,  // [A, 1]
    float* __restrict__ out)       // [S, A]
{
    __shared__ __align__(16) float  w1p[H_DIM * 8];        // [j][0..4]=W1t, [j][5]=b1
    __shared__ __align__(16) __half W2h[H_DIM * H_DIM];    // [jin][kout] fp16
    __shared__ __align__(16) float  b2s[H_DIM];
    __shared__ __align__(16) float  w3s[H_DIM];
    __shared__ float b3sh;
    __shared__ __align__(16) __half hbuf[NWARPS][H_DIM * HB_STRIDE]; // per-warp h1 tile

    const int a    = blockIdx.x;
    const int tid  = threadIdx.x;
    const int warp = tid >> 5;
    const int lane = tid & 31;
    const int gid  = lane >> 2;    // 0..7  (fragment row group)
    const int t2   = (lane & 3) * 2; // 0,2,4,6 (fragment col pair)

    // ---- stage weights ----
    for (int idx = tid; idx < H_DIM * 8; idx += NTHREADS) {
        int j = idx >> 3, slot = idx & 7;
        float v = 0.0f;
        if (slot < I_DIM)       v = W1[a * I_DIM * H_DIM + slot * H_DIM + j];
        else if (slot == I_DIM) v = b1[a * H_DIM + j];
        w1p[idx] = v;
    }
    for (int idx = tid; idx < H_DIM * H_DIM; idx += NTHREADS)
        W2h[idx] = __float2half(W2[a * H_DIM * H_DIM + idx]);
    if (tid < H_DIM) {
        b2s[tid] = b2[a * H_DIM + tid];
        w3s[tid] = W3[a * H_DIM + tid];
    }
    if (tid == 0) b3sh = b3[a];
    __syncthreads();

    // ---- per-thread B fragments (built once; W2h[k][n], col n = gid) ----
    // mma m16n8k16 B frag: b0 = {k=t2, t2+1}, b1 = {k=t2+8, t2+9}; k-step adds 16.
    uint32_t bf[16]; // [ (nt*2 + ks)*2 + {0,1} ]
    #pragma unroll
    for (int nt = 0; nt < 4; nt++)
        #pragma unroll
        for (int ks = 0; ks < 2; ks++) {
            int n  = nt * 8 + gid;
            int k0 = ks * 16 + t2;
            __half2 p0 = __halves2half2(W2h[k0 * H_DIM + n],       W2h[(k0 + 1) * H_DIM + n]);
            __half2 p1 = __halves2half2(W2h[(k0 + 8) * H_DIM + n], W2h[(k0 + 9) * H_DIM + n]);
            bf[(nt * 2 + ks) * 2 + 0] = *reinterpret_cast<uint32_t*>(&p0);
            bf[(nt * 2 + ks) * 2 + 1] = *reinterpret_cast<uint32_t*>(&p1);
        }
    // epilogue constants for this thread's C columns: col = nt*8 + t2 + {0,1}
    float b2v[8], w3v[8];
    #pragma unroll
    for (int nt = 0; nt < 4; nt++) {
        b2v[nt * 2 + 0] = b2s[nt * 8 + t2 + 0];
        b2v[nt * 2 + 1] = b2s[nt * 8 + t2 + 1];
        w3v[nt * 2 + 0] = w3s[nt * 8 + t2 + 0];
        w3v[nt * 2 + 1] = w3s[nt * 8 + t2 + 1];
    }
    const float b3v = b3sh;
    __half* hb = hbuf[warp];

    // ---- main loop: each warp owns groups of 32 structs ----
    #pragma unroll 1
    for (int grp = warp; grp < GROUPS; grp += NWARPS) {
        const int s0 = grp * 32;
        const int s  = s0 + lane;

        float gv[I_DIM];
        if (s < S_TOT) {
            const float* gp = g + (size_t)s * (A_TOT * I_DIM) + a * I_DIM;
            #pragma unroll
            for (int i = 0; i < I_DIM; i++) gv[i] = gp[i];
        } else {
            #pragma unroll
            for (int i = 0; i < I_DIM; i++) gv[i] = 0.0f;
        }

        // layer 1 (scalar fp32), rounded to fp16 into hbuf[lane][j]
        // unroll 1: round-8 lesson (full unroll -> LDS hoist -> spill)
        float hprev = 0.0f;
        #pragma unroll 1
        for (int j = 0; j < H_DIM; j++) {
            const float4* w1row = (const float4*)&w1p[j * 8];
            const float4 wlo = w1row[0];
            const float4 whi = w1row[1];
            float a1 = whi.y;                  // b1_j
            a1 = fmaf(gv[0], wlo.x, a1);
            a1 = fmaf(gv[1], wlo.y, a1);
            a1 = fmaf(gv[2], wlo.z, a1);
            a1 = fmaf(gv[3], wlo.w, a1);
            a1 = fmaf(gv[4], whi.x, a1);
            const float h = tanh_fast(a1);
            if (j & 1) {
                __half2 hp = __floats2half2_rn(hprev, h);
                *reinterpret_cast<__half2*>(hb + lane * HB_STRIDE + (j - 1)) = hp;
            } else {
                hprev = h;
            }
        }
        __syncwarp();

        // layer 2 via HMMA + layer 3 epilogue, two 16-row tiles
        #pragma unroll
        for (int T = 0; T < 2; T++) {
            const int r = T * 16 + gid;
            float cc[4][4];
            #pragma unroll
            for (int nt = 0; nt < 4; nt++)
                #pragma unroll
                for (int x = 0; x < 4; x++) cc[nt][x] = 0.0f;

            // K-step 0 (k = 0..15)
            uint32_t A0 = *reinterpret_cast<const uint32_t*>(hb + r * HB_STRIDE + t2);
            uint32_t A1 = *reinterpret_cast<const uint32_t*>(hb + (r + 8) * HB_STRIDE + t2);
            uint32_t A2 = *reinterpret_cast<const uint32_t*>(hb + r * HB_STRIDE + t2 + 8);
            uint32_t A3 = *reinterpret_cast<const uint32_t*>(hb + (r + 8) * HB_STRIDE + t2 + 8);
            #pragma unroll
            for (int nt = 0; nt < 4; nt++)
                mma16816(cc[nt][0], cc[nt][1], cc[nt][2], cc[nt][3],
                         A0, A1, A2, A3, bf[(nt * 2 + 0) * 2], bf[(nt * 2 + 0) * 2 + 1]);

            // K-step 1 (k = 16..31)
            A0 = *reinterpret_cast<const uint32_t*>(hb + r * HB_STRIDE + 16 + t2);
            A1 = *reinterpret_cast<const uint32_t*>(hb + (r + 8) * HB_STRIDE + 16 + t2);
            A2 = *reinterpret_cast<const uint32_t*>(hb + r * HB_STRIDE + 16 + t2 + 8);
            A3 = *reinterpret_cast<const uint32_t*>(hb + (r + 8) * HB_STRIDE + 16 + t2 + 8);
            #pragma unroll
            for (int nt = 0; nt < 4; nt++)
                mma16816(cc[nt][0], cc[nt][1], cc[nt][2], cc[nt][3],
                         A0, A1, A2, A3, bf[(nt * 2 + 1) * 2], bf[(nt * 2 + 1) * 2 + 1]);

            // epilogue: tanh + dot with W3; c0/c1 row=gid, c2/c3 row=gid+8
            float e_lo = 0.0f, e_hi = 0.0f;
            #pragma unroll
            for (int nt = 0; nt < 4; nt++) {
                e_lo = fmaf(tanh_fast(cc[nt][0] + b2v[nt * 2 + 0]), w3v[nt * 2 + 0], e_lo);
                e_lo = fmaf(tanh_fast(cc[nt][1] + b2v[nt * 2 + 1]), w3v[nt * 2 + 1], e_lo);
                e_hi = fmaf(tanh_fast(cc[nt][2] + b2v[nt * 2 + 0]), w3v[nt * 2 + 0], e_hi);
                e_hi = fmaf(tanh_fast(cc[nt][3] + b2v[nt * 2 + 1]), w3v[nt * 2 + 1], e_hi);
            }
            e_lo += __shfl_xor_sync(0xffffffffu, e_lo, 1);
            e_lo += __shfl_xor_sync(0xffffffffu, e_lo, 2);
            e_hi += __shfl_xor_sync(0xffffffffu, e_hi, 1);
            e_hi += __shfl_xor_sync(0xffffffffu, e_hi, 2);

            if ((lane & 3) == 0) {
                const int sa = s0 + T * 16 + gid;
                if (sa < S_TOT)     out[(size_t)sa * A_TOT + a]       = e_lo + b3v;
                if (sa + 8 < S_TOT) out[(size_t)(sa + 8) * A_TOT + a] = e_hi + b3v;
            }
        }
        __syncwarp();
    }
}

extern "C" void kernel_launch(void* const* d_in, const int* in_sizes, int n_in,
                              void* d_out, int out_size) {
    const float* g  = (const float*)d_in[0];
    const float* W1 = (const float*)d_in[1];
    const float* b1 = (const float*)d_in[2];
    const float* W2 = (const float*)d_in[3];
    const float* b2 = (const float*)d_in[4];
    const float* W3 = (const float*)d_in[5];
    const float* b3 = (const float*)d_in[6];
    float* out = (float*)d_out;

    mlp_kernel<<<A_TOT, NTHREADS>>>(g, W1, b1, W2, b2, W3, b3, out);
}

// round 15
// speedup vs baseline: 3.5337x; 1.3901x over previous
#include <cuda_runtime.h>
#include <cuda_fp16.h>
#include <cstdint>

#define S_TOT 2000
#define A_TOT 1000
#define I_DIM 5
#define H_DIM 32
#define NTHREADS 256
#define NWARPS 8
#define GROUPS ((S_TOT + 31) / 32)    // 63 groups of 32 structs

__device__ __forceinline__ float tanh_fast(float x) {
    asm("tanh.approx.f32 %0, %0;" : "+f"(x));
    return x;
}
__device__ __forceinline__ uint32_t f2tf32(float x) {
    uint32_t r; asm("cvt.rna.tf32.f32 %0, %1;" : "=r"(r) : "f"(x)); return r;
}
__device__ __forceinline__ uint32_t packh2(float lo, float hi) {
    __half2 p = __floats2half2_rn(lo, hi);
    return *reinterpret_cast<uint32_t*>(&p);
}

// layer-1: D(16x8 f32) = A(16x8 tf32, row) * B(8x8 tf32, col) + C
__device__ __forceinline__ void mma_tf32(float* c,
                                         uint32_t a0, uint32_t a1, uint32_t a2, uint32_t a3,
                                         uint32_t b0, uint32_t b1) {
    asm volatile(
        "mma.sync.aligned.m16n8k8.row.col.f32.tf32.tf32.f32 "
        "{%0,%1,%2,%3}, {%4,%5,%6,%7}, {%8,%9}, {%0,%1,%2,%3};"
        : "+f"(c[0]), "+f"(c[1]), "+f"(c[2]), "+f"(c[3])
        : "r"(a0), "r"(a1), "r"(a2), "r"(a3), "r"(b0), "r"(b1));
}
// layer-2: D(16x8 f32) = A(16x16 f16, row) * B(16x8 f16, col) + C
__device__ __forceinline__ void mma16816(float* c,
                                         uint32_t a0, uint32_t a1, uint32_t a2, uint32_t a3,
                                         uint32_t b0, uint32_t b1) {
    asm volatile(
        "mma.sync.aligned.m16n8k16.row.col.f32.f16.f16.f32 "
        "{%0,%1,%2,%3}, {%4,%5,%6,%7}, {%8,%9}, {%0,%1,%2,%3};"
        : "+f"(c[0]), "+f"(c[1]), "+f"(c[2]), "+f"(c[3])
        : "r"(a0), "r"(a1), "r"(a2), "r"(a3), "r"(b0), "r"(b1));
}

__global__ __launch_bounds__(NTHREADS, 2) void mlp_kernel(
    const float* __restrict__ g,   // [S, A, I]
    const float* __restrict__ W1,  // [A, I, H]
    const float* __restrict__ b1,  // [A, H]
    const float* __restrict__ W2,  // [A, H, H]
    const float* __restrict__ b2,  // [A, H]
    const float* __restrict__ W3,  // [A, H, 1]
    const float* __restrict__ b3,  // [A, 1]
    float* __restrict__ out)       // [S, A]
{
    __shared__ __align__(16) __half W2h[H_DIM * H_DIM];    // [k][n] fp16 staging

    const int a    = blockIdx.x;
    const int tid  = threadIdx.x;
    const int warp = tid >> 5;
    const int lane = tid & 31;
    const int gid  = lane >> 2;      // fragment row group 0..7
    const int q    = lane & 3;       // tf32 k-lane 0..3
    const int t2   = q * 2;          // f16 frag col pair 0,2,4,6

    for (int idx = tid; idx < H_DIM * H_DIM; idx += NTHREADS)
        W2h[idx] = __float2half(W2[a * H_DIM * H_DIM + idx]);
    __syncthreads();

    // ---- per-thread persistent fragments / constants ----
    // layer-2 B frags (fp16): bf[(nt*2+ks)*2 + {0,1}]
    uint32_t bf[16];
    #pragma unroll
    for (int nt = 0; nt < 4; nt++)
        #pragma unroll
        for (int ks = 0; ks < 2; ks++) {
            int n  = nt * 8 + gid;
            int k0 = ks * 16 + t2;
            bf[(nt * 2 + ks) * 2 + 0] =
                packh2(__half2float(W2h[k0 * H_DIM + n]),       __half2float(W2h[(k0 + 1) * H_DIM + n]));
            bf[(nt * 2 + ks) * 2 + 1] =
                packh2(__half2float(W2h[(k0 + 8) * H_DIM + n]), __half2float(W2h[(k0 + 9) * H_DIM + n]));
        }
    // layer-1 B frags (tf32): wb[nt][0] = W1[i=q][col], wb[nt][1] = W1[i=q+4][col] (pad 0)
    uint32_t wb[4][2];
    #pragma unroll
    for (int nt = 0; nt < 4; nt++) {
        int col = nt * 8 + gid;
        wb[nt][0] = f2tf32(W1[a * I_DIM * H_DIM + q * H_DIM + col]);
        wb[nt][1] = (q == 0) ? f2tf32(W1[a * I_DIM * H_DIM + 4 * H_DIM + col]) : 0u;
    }
    // per-column constants (cols nt*8 + t2 + {0,1})
    float b1v[8], b2v[8], w3v[8];
    #pragma unroll
    for (int nt = 0; nt < 4; nt++) {
        int c0 = nt * 8 + t2;
        b1v[nt * 2 + 0] = b1[a * H_DIM + c0];     b1v[nt * 2 + 1] = b1[a * H_DIM + c0 + 1];
        b2v[nt * 2 + 0] = b2[a * H_DIM + c0];     b2v[nt * 2 + 1] = b2[a * H_DIM + c0 + 1];
        w3v[nt * 2 + 0] = W3[a * H_DIM + c0];     w3v[nt * 2 + 1] = W3[a * H_DIM + c0 + 1];
    }
    const float b3v = b3[a];

    // ---- main loop: pure register pipeline, no smem ----
    #pragma unroll 1
    for (int grp = warp; grp < GROUPS; grp += NWARPS) {
        const int s0 = grp * 32;
        #pragma unroll
        for (int T = 0; T < 2; T++) {
            const int row0 = s0 + T * 16 + gid;
            const int row1 = row0 + 8;
            const float* g0p = g + (size_t)row0 * (A_TOT * I_DIM) + a * I_DIM;
            const float* g1p = g + (size_t)row1 * (A_TOT * I_DIM) + a * I_DIM;
            // A frag (tf32): a0=(row0, i=q) a1=(row1, q) a2=(row0, q+4) a3=(row1, q+4)
            const uint32_t A0 = (row0 < S_TOT) ? f2tf32(g0p[q]) : 0u;
            const uint32_t A1 = (row1 < S_TOT) ? f2tf32(g1p[q]) : 0u;
            const uint32_t A2 = (q == 0 && row0 < S_TOT) ? f2tf32(g0p[4]) : 0u;
            const uint32_t A3 = (q == 0 && row1 < S_TOT) ? f2tf32(g1p[4]) : 0u;

            // layer 1: 4 n-tiles of m16n8k8 tf32
            float c1v[4][4];
            #pragma unroll
            for (int nt = 0; nt < 4; nt++) {
                c1v[nt][0] = c1v[nt][1] = c1v[nt][2] = c1v[nt][3] = 0.0f;
                mma_tf32(c1v[nt], A0, A1, A2, A3, wb[nt][0], wb[nt][1]);
            }

            // bias + tanh + pack into layer-2 A frags (C layout == A layout)
            uint32_t Af[2][4];
            #pragma unroll
            for (int ck = 0; ck < 2; ck++) {
                const int na = 2 * ck, nb = 2 * ck + 1;
                Af[ck][0] = packh2(tanh_fast(c1v[na][0] + b1v[na * 2 + 0]),
                                   tanh_fast(c1v[na][1] + b1v[na * 2 + 1]));
                Af[ck][1] = packh2(tanh_fast(c1v[na][2] + b1v[na * 2 + 0]),
                                   tanh_fast(c1v[na][3] + b1v[na * 2 + 1]));
                Af[ck][2] = packh2(tanh_fast(c1v[nb][0] + b1v[nb * 2 + 0]),
                                   tanh_fast(c1v[nb][1] + b1v[nb * 2 + 1]));
                Af[ck][3] = packh2(tanh_fast(c1v[nb][2] + b1v[nb * 2 + 0]),
                                   tanh_fast(c1v[nb][3] + b1v[nb * 2 + 1]));
            }

            // layer 2: 4 col-tiles x 2 k-chunks of m16n8k16 fp16
            float cc[4][4];
            #pragma unroll
            for (int nt = 0; nt < 4; nt++) {
                cc[nt][0] = cc[nt][1] = cc[nt][2] = cc[nt][3] = 0.0f;
                mma16816(cc[nt], Af[0][0], Af[0][1], Af[0][2], Af[0][3],
                         bf[(nt * 2 + 0) * 2], bf[(nt * 2 + 0) * 2 + 1]);
                mma16816(cc[nt], Af[1][0], Af[1][1], Af[1][2], Af[1][3],
                         bf[(nt * 2 + 1) * 2], bf[(nt * 2 + 1) * 2 + 1]);
            }

            // epilogue: tanh + W3 dot + quad reduce
            float e_lo = 0.0f, e_hi = 0.0f;
            #pragma unroll
            for (int nt = 0; nt < 4; nt++) {
                e_lo = fmaf(tanh_fast(cc[nt][0] + b2v[nt * 2 + 0]), w3v[nt * 2 + 0], e_lo);
                e_lo = fmaf(tanh_fast(cc[nt][1] + b2v[nt * 2 + 1]), w3v[nt * 2 + 1], e_lo);
                e_hi = fmaf(tanh_fast(cc[nt][2] + b2v[nt * 2 + 0]), w3v[nt * 2 + 0], e_hi);
                e_hi = fmaf(tanh_fast(cc[nt][3] + b2v[nt * 2 + 1]), w3v[nt * 2 + 1], e_hi);
            }
            e_lo += __shfl_xor_sync(0xffffffffu, e_lo, 1);
            e_lo += __shfl_xor_sync(0xffffffffu, e_lo, 2);
            e_hi += __shfl_xor_sync(0xffffffffu, e_hi, 1);
            e_hi += __shfl_xor_sync(0xffffffffu, e_hi, 2);

            if (q == 0) {
                if (row0 < S_TOT) out[(size_t)row0 * A_TOT + a] = e_lo + b3v;
                if (row1 < S_TOT) out[(size_t)row1 * A_TOT + a] = e_hi + b3v;
            }
        }
    }
}

extern "C" void kernel_launch(void* const* d_in, const int* in_sizes, int n_in,
                              void* d_out, int out_size) {
    const float* g  = (const float*)d_in[0];
    const float* W1 = (const float*)d_in[1];
    const float* b1 = (const float*)d_in[2];
    const float* W2 = (const float*)d_in[3];
    const float* b2 = (const float*)d_in[4];
    const float* W3 = (const float*)d_in[5];
    const float* b3 = (const float*)d_in[6];
    float* out = (float*)d_out;

    mlp_kernel<<<A_TOT, NTHREADS>>>(g, W1, b1, W2, b2, W3, b3, out);
}

// round 17
// speedup vs baseline: 5.0485x; 1.4287x over previous
#include <cuda_runtime.h>
#include <cuda_fp16.h>
#include <cstdint>

#define S_TOT 2000
#define A_TOT 1000
#define I_DIM 5
#define H_DIM 32
#define NTHREADS 256
#define NWARPS 8
#define GROUPS ((S_TOT + 31) / 32)    // 63 groups of 32 structs

__device__ __forceinline__ float tanh_fast(float x) {
    asm("tanh.approx.f32 %0, %0;" : "+f"(x));
    return x;
}
__device__ __forceinline__ uint32_t f2tf32(float x) {
    uint32_t r; asm("cvt.rna.tf32.f32 %0, %1;" : "=r"(r) : "f"(x)); return r;
}
__device__ __forceinline__ uint32_t packh2(float lo, float hi) {
    __half2 p = __floats2half2_rn(lo, hi);
    return *reinterpret_cast<uint32_t*>(&p);
}

// layer-1: D(16x8 f32) = A(16x8 tf32, row) * B(8x8 tf32, col) + C
__device__ __forceinline__ void mma_tf32(float* c,
                                         uint32_t a0, uint32_t a1, uint32_t a2, uint32_t a3,
                                         uint32_t b0, uint32_t b1) {
    asm volatile(
        "mma.sync.aligned.m16n8k8.row.col.f32.tf32.tf32.f32 "
        "{%0,%1,%2,%3}, {%4,%5,%6,%7}, {%8,%9}, {%0,%1,%2,%3};"
        : "+f"(c[0]), "+f"(c[1]), "+f"(c[2]), "+f"(c[3])
        : "r"(a0), "r"(a1), "r"(a2), "r"(a3), "r"(b0), "r"(b1));
}
// layer-2: D(16x8 f32) = A(16x16 f16, row) * B(16x8 f16, col) + C
__device__ __forceinline__ void mma16816(float* c,
                                         uint32_t a0, uint32_t a1, uint32_t a2, uint32_t a3,
                                         uint32_t b0, uint32_t b1) {
    asm volatile(
        "mma.sync.aligned.m16n8k16.row.col.f32.f16.f16.f32 "
        "{%0,%1,%2,%3}, {%4,%5,%6,%7}, {%8,%9}, {%0,%1,%2,%3};"
        : "+f"(c[0]), "+f"(c[1]), "+f"(c[2]), "+f"(c[3])
        : "r"(a0), "r"(a1), "r"(a2), "r"(a3), "r"(b0), "r"(b1));
}

// 3 blocks/SM (85-reg cap): occupancy lever; persistent state ~50 regs.
__global__ __launch_bounds__(NTHREADS, 3) void mlp_kernel(
    const float* __restrict__ g,   // [S, A, I]
    const float* __restrict__ W1,  // [A, I, H]
    const float* __restrict__ b1,  // [A, H]
    const float* __restrict__ W2,  // [A, H, H]
    const float* __restrict__ b2,  // [A, H]
    const float* __restrict__ W3,  // [A, H, 1]
    const float* __restrict__ b3,  // [A, 1]
    float* __restrict__ out)       // [S, A]
{
    __shared__ __align__(16) __half W2h[H_DIM * H_DIM];    // [k][n] fp16 staging

    const int a    = blockIdx.x;
    const int tid  = threadIdx.x;
    const int warp = tid >> 5;
    const int lane = tid & 31;
    const int gid  = lane >> 2;      // fragment row group 0..7
    const int q    = lane & 3;       // tf32 k-lane 0..3
    const int t2   = q * 2;          // f16 frag col pair 0,2,4,6

    for (int idx = tid; idx < H_DIM * H_DIM; idx += NTHREADS)
        W2h[idx] = __float2half(W2[a * H_DIM * H_DIM + idx]);
    __syncthreads();

    // ---- per-thread persistent fragments / constants ----
    uint32_t bf[16];
    #pragma unroll
    for (int nt = 0; nt < 4; nt++)
        #pragma unroll
        for (int ks = 0; ks < 2; ks++) {
            int n  = nt * 8 + gid;
            int k0 = ks * 16 + t2;
            bf[(nt * 2 + ks) * 2 + 0] =
                packh2(__half2float(W2h[k0 * H_DIM + n]),       __half2float(W2h[(k0 + 1) * H_DIM + n]));
            bf[(nt * 2 + ks) * 2 + 1] =
                packh2(__half2float(W2h[(k0 + 8) * H_DIM + n]), __half2float(W2h[(k0 + 9) * H_DIM + n]));
        }
    uint32_t wb[4][2];
    #pragma unroll
    for (int nt = 0; nt < 4; nt++) {
        int col = nt * 8 + gid;
        wb[nt][0] = f2tf32(W1[a * I_DIM * H_DIM + q * H_DIM + col]);
        wb[nt][1] = (q == 0) ? f2tf32(W1[a * I_DIM * H_DIM + 4 * H_DIM + col]) : 0u;
    }
    float b1v[8], b2v[8], w3v[8];
    #pragma unroll
    for (int nt = 0; nt < 4; nt++) {
        int c0 = nt * 8 + t2;
        b1v[nt * 2 + 0] = b1[a * H_DIM + c0];     b1v[nt * 2 + 1] = b1[a * H_DIM + c0 + 1];
        b2v[nt * 2 + 0] = b2[a * H_DIM + c0];     b2v[nt * 2 + 1] = b2[a * H_DIM + c0 + 1];
        w3v[nt * 2 + 0] = W3[a * H_DIM + c0];     w3v[nt * 2 + 1] = W3[a * H_DIM + c0 + 1];
    }
    const float b3v = b3[a];
    const float* gbase = g + a * I_DIM;

    // ---- prefetch group g-values into registers (8 floats/thread) ----
    // pf[T*4 + {0,1,2,3}] = {g[row0][q], g[row1][q], g[row0][4], g[row1][4]}
    float pf[8];
    auto load_group = [&](int grp, float* dst) {
        const int s0 = grp * 32;
        #pragma unroll
        for (int T = 0; T < 2; T++) {
            const int row0 = s0 + T * 16 + gid;
            const int row1 = row0 + 8;
            const float* g0p = gbase + (size_t)row0 * (A_TOT * I_DIM);
            const float* g1p = gbase + (size_t)row1 * (A_TOT * I_DIM);
            dst[T * 4 + 0] = (row0 < S_TOT) ? g0p[q] : 0.0f;
            dst[T * 4 + 1] = (row1 < S_TOT) ? g1p[q] : 0.0f;
            dst[T * 4 + 2] = (q == 0 && row0 < S_TOT) ? g0p[4] : 0.0f;
            dst[T * 4 + 3] = (q == 0 && row1 < S_TOT) ? g1p[4] : 0.0f;
        }
    };

    load_group(warp, pf);

    // ---- main loop: register pipeline with next-group prefetch ----
    #pragma unroll 1
    for (int grp = warp; grp < GROUPS; grp += NWARPS) {
        float cur[8];
        #pragma unroll
        for (int i = 0; i < 8; i++) cur[i] = pf[i];

        // issue NEXT group's loads now; they overlap this group's MMA chain
        if (grp + NWARPS < GROUPS) load_group(grp + NWARPS, pf);

        const int s0 = grp * 32;
        #pragma unroll
        for (int T = 0; T < 2; T++) {
            const int row0 = s0 + T * 16 + gid;
            const int row1 = row0 + 8;
            const uint32_t A0 = f2tf32(cur[T * 4 + 0]);
            const uint32_t A1 = f2tf32(cur[T * 4 + 1]);
            const uint32_t A2 = f2tf32(cur[T * 4 + 2]);
            const uint32_t A3 = f2tf32(cur[T * 4 + 3]);

            // layer 1: 4 n-tiles of m16n8k8 tf32
            float c1v[4][4];
            #pragma unroll
            for (int nt = 0; nt < 4; nt++) {
                c1v[nt][0] = c1v[nt][1] = c1v[nt][2] = c1v[nt][3] = 0.0f;
                mma_tf32(c1v[nt], A0, A1, A2, A3, wb[nt][0], wb[nt][1]);
            }

            // bias + tanh + pack into layer-2 A frags (C layout == A layout)
            uint32_t Af[2][4];
            #pragma unroll
            for (int ck = 0; ck < 2; ck++) {
                const int na = 2 * ck, nb = 2 * ck + 1;
                Af[ck][0] = packh2(tanh_fast(c1v[na][0] + b1v[na * 2 + 0]),
                                   tanh_fast(c1v[na][1] + b1v[na * 2 + 1]));
                Af[ck][1] = packh2(tanh_fast(c1v[na][2] + b1v[na * 2 + 0]),
                                   tanh_fast(c1v[na][3] + b1v[na * 2 + 1]));
                Af[ck][2] = packh2(tanh_fast(c1v[nb][0] + b1v[nb * 2 + 0]),
                                   tanh_fast(c1v[nb][1] + b1v[nb * 2 + 1]));
                Af[ck][3] = packh2(tanh_fast(c1v[nb][2] + b1v[nb * 2 + 0]),
                                   tanh_fast(c1v[nb][3] + b1v[nb * 2 + 1]));
            }

            // layer 2: 4 col-tiles x 2 k-chunks of m16n8k16 fp16
            float cc[4][4];
            #pragma unroll
            for (int nt = 0; nt < 4; nt++) {
                cc[nt][0] = cc[nt][1] = cc[nt][2] = cc[nt][3] = 0.0f;
                mma16816(cc[nt], Af[0][0], Af[0][1], Af[0][2], Af[0][3],
                         bf[(nt * 2 + 0) * 2], bf[(nt * 2 + 0) * 2 + 1]);
                mma16816(cc[nt], Af[1][0], Af[1][1], Af[1][2], Af[1][3],
                         bf[(nt * 2 + 1) * 2], bf[(nt * 2 + 1) * 2 + 1]);
            }

            // epilogue: tanh + W3 dot + quad reduce
            float e_lo = 0.0f, e_hi = 0.0f;
            #pragma unroll
            for (int nt = 0; nt < 4; nt++) {
                e_lo = fmaf(tanh_fast(cc[nt][0] + b2v[nt * 2 + 0]), w3v[nt * 2 + 0], e_lo);
                e_lo = fmaf(tanh_fast(cc[nt][1] + b2v[nt * 2 + 1]), w3v[nt * 2 + 1], e_lo);
                e_hi = fmaf(tanh_fast(cc[nt][2] + b2v[nt * 2 + 0]), w3v[nt * 2 + 0], e_hi);
                e_hi = fmaf(tanh_fast(cc[nt][3] + b2v[nt * 2 + 1]), w3v[nt * 2 + 1], e_hi);
            }
            e_lo += __shfl_xor_sync(0xffffffffu, e_lo, 1);
            e_lo += __shfl_xor_sync(0xffffffffu, e_lo, 2);
            e_hi += __shfl_xor_sync(0xffffffffu, e_hi, 1);
            e_hi += __shfl_xor_sync(0xffffffffu, e_hi, 2);

            if (q == 0) {
                if (row0 < S_TOT) out[(size_t)row0 * A_TOT + a] = e_lo + b3v;
                if (row1 < S_TOT) out[(size_t)row1 * A_TOT + a] = e_hi + b3v;
            }
        }
    }
}

extern "C" void kernel_launch(void* const* d_in, const int* in_sizes, int n_in,
                              void* d_out, int out_size) {
    const float* g  = (const float*)d_in[0];
    const float* W1 = (const float*)d_in[1];
    const float* b1 = (const float*)d_in[2];
    const float* W2 = (const float*)d_in[3];
    const float* b2 = (const float*)d_in[4];
    const float* W3 = (const float*)d_in[5];
    const float* b3 = (const float*)d_in[6];
    float* out = (float*)d_out;

    mlp_kernel<<<A_TOT, NTHREADS>>>(g, W1, b1, W2, b2, W3, b3, out);
}